// round 9
// baseline (speedup 1.0000x reference)
#include <cuda_runtime.h>

#define NB   48
#define CHN  3
#define HH   256
#define WW   256
#define NIC  (NB*CHN)
#define NPIX (HH*WW)

#define TH   32
#define TW   64
#define IHH  42           // TH + 10
#define IWW  74           // TW + 10
#define XP2  75           // float2 plane stride (odd -> conflict-free LDS.64)
#define VP4  75           // float4-equiv plane stride (conflict-free LDS.128)
#define NTHR 320
#define NTILE 32
#define NWORK (NTILE * NIC)   // 4608 tiles
#define GRID  444             // 3 blocks/SM * 148 SMs -> single persistent wave

#define SM_FLOATS (2*IHH*XP2 + 4*TH*VP4 + 16)
#define SM_BYTES  (SM_FLOATS * 4)

typedef unsigned long long u64;

__device__ double g_acc;
__device__ unsigned int g_count = 0;
__device__ unsigned char g_wbonus[NB * NPIX];   // 3*m0 + 3*m1 + 2*m2 in [0,8]

// Normalized 1D Gaussian, k=11, sigma=1.5 (symmetric: G[t] == G[10-t])
__device__ constexpr float G[11] = {
    0.00102838f, 0.00759876f, 0.03600078f, 0.10936071f, 0.21300554f,
    0.26601172f,
    0.21300554f, 0.10936071f, 0.03600078f, 0.00759876f, 0.00102838f
};

// ---- packed f32x2 helpers (Blackwell FFMA2 path) ----
__device__ __forceinline__ u64 ffma2(u64 a, u64 b, u64 c) {
    u64 d;
    asm("fma.rn.f32x2 %0, %1, %2, %3;" : "=l"(d) : "l"(a), "l"(b), "l"(c));
    return d;
}
__device__ __forceinline__ u64 pack2(float lo, float hi) {
    u64 d;
    asm("mov.b64 %0, {%1, %2};" : "=l"(d) : "f"(lo), "f"(hi));
    return d;
}
__device__ __forceinline__ void unpack2(u64 v, float& lo, float& hi) {
    asm("mov.b64 {%0, %1}, %2;" : "=f"(lo), "=f"(hi) : "l"(v));
}

// 8 rows per block. 192 threads evaluate (row, edge) pairs; 24 compact
// crossing thresholds; 8 uniform per-row pixel passes.
__global__ void __launch_bounds__(WW) wmap_kernel(const float* __restrict__ lmk) {
    const int rbase = blockIdx.x * 8;
    const int n     = blockIdx.y;
    const int tid   = threadIdx.x;

    __shared__ float ethr[8][24];
    __shared__ int   eflg[8][24];
    __shared__ float clist[8][3][12];
    __shared__ int   ccnt[8][3];
    __shared__ float bxmin[3], bxmax[3], fymn[3], fymx[3];
    __shared__ int   pval[3];

    if (rbase == 0 && n == 0 && tid == 255) g_acc = 0.0;  // zero per replay

    const float* L = lmk + n * 136;

    if (tid < 192) {
        int rr = tid / 24, e = tid % 24;
        float Y = (float)(rbase + rr);
        int p    = (e < 6) ? 0 : ((e < 12) ? 1 : 2);
        int base = (p == 0) ? 36 : ((p == 1) ? 42 : 48);
        int cnt  = (p == 2) ? 12 : 6;
        int i    = e - ((p == 0) ? 0 : ((p == 1) ? 6 : 12));
        int j    = (i + 1 == cnt) ? 0 : i + 1;
        float x1 = L[2*(base+i)], y1 = L[2*(base+i)+1];
        float x2 = L[2*(base+j)], y2 = L[2*(base+j)+1];
        eflg[rr][e] = ((y1 > Y) != (y2 > Y)) ? 1 : 0;
        ethr[rr][e] = (x2 - x1) * (Y - y1) / (y2 - y1 + 1e-6f) + x1;
    } else if (tid < 195) {
        int p    = tid - 192;
        int base = (p == 0) ? 36 : ((p == 1) ? 42 : 48);
        int cnt  = (p == 2) ? 12 : 6;
        float mnx = 1e30f, mxx = -1e30f, mny = 1e30f, mxy = -1e30f;
        for (int i = 0; i < cnt; i++) {
            float x = L[2*(base+i)], y = L[2*(base+i)+1];
            mnx = fminf(mnx, x); mxx = fmaxf(mxx, x);
            mny = fminf(mny, y); mxy = fmaxf(mxy, y);
        }
        float fxmin = floorf(mnx), fxmax = floorf(mxx);
        fymn[p] = floorf(mny);  fymx[p] = floorf(mxy);
        pval[p] = ((fxmin >= 0.f) && (fymn[p] >= 0.f) &&
                   (fxmax < (float)WW) && (fymx[p] < (float)HH)) ? 1 : 0;
        bxmin[p] = fxmin; bxmax[p] = fxmax;
    }
    __syncthreads();

    if (tid < 24) {
        int rr = tid / 3, p = tid % 3;
        float Y = (float)(rbase + rr);
        int s  = (p == 0) ? 0 : ((p == 1) ? 6 : 12);
        int cn = (p == 2) ? 12 : 6;
        int c = 0;
        if (pval[p] && (Y >= fymn[p]) && (Y < fymx[p])) {
            for (int i = 0; i < cn; i++)
                if (eflg[rr][s + i]) clist[rr][p][c++] = ethr[rr][s + i];
        }
        ccnt[rr][p] = c;
    }
    __syncthreads();

    unsigned char* dst = g_wbonus + n * NPIX + rbase * WW;
    float X = (float)tid;
    #pragma unroll
    for (int r = 0; r < 8; r++) {
        int c0 = ccnt[r][0], c1 = ccnt[r][1], c2 = ccnt[r][2];
        int bonus = 0;
        if ((c0 | c1 | c2) != 0) {
            int cnt = 0;
            for (int i = 0; i < c0; i++) cnt += (X < clist[r][0][i]) ? 1 : 0;
            if ((cnt & 1) && (X >= bxmin[0]) && (X < bxmax[0])) bonus += 3;
            cnt = 0;
            for (int i = 0; i < c1; i++) cnt += (X < clist[r][1][i]) ? 1 : 0;
            if ((cnt & 1) && (X >= bxmin[1]) && (X < bxmax[1])) bonus += 3;
            cnt = 0;
            for (int i = 0; i < c2; i++) cnt += (X < clist[r][2][i]) ? 1 : 0;
            if ((cnt & 1) && (X >= bxmin[2]) && (X < bxmax[2])) bonus += 2;
        }
        dst[r * WW + tid] = (unsigned char)bonus;
    }
}

// Persistent fused main with packed f32x2 FMA: conv fields paired as
// (mu_x,mu_y) and (x^2+y^2, x*y) in 64-bit registers -> 2 FFMA2 per tap
// instead of 4 FFMA.
__global__ void __launch_bounds__(NTHR, 3) main_kernel(const float* __restrict__ pred,
                                                       const float* __restrict__ target,
                                                       float* __restrict__ out) {
    extern __shared__ float sm[];
    float2*     sXY  = (float2*)sm;                      // [IHH][XP2]
    ulonglong2* Vb   = (ulonglong2*)(sm + 2*IHH*XP2);    // [TH][VP4] (mu-pair, sq-pair)
    float*      red  = sm + 2*IHH*XP2 + 4*TH*VP4;        // [10]

    const int tid = threadIdx.x;

    // Packed Gaussian coefficient pairs (g,g); 6 unique by symmetry.
    u64 G2[6];
    #pragma unroll
    for (int t = 0; t < 6; t++) G2[t] = pack2(G[t], G[t]);

    // Phase-1 fixed decomposition
    const int  c1    = tid % 80;
    const int  r1    = tid / 80;
    const bool cok   = (c1 < IWW);
    const bool cint  = (c1 >= 5) && (c1 < IWW - 5);
    // Phase-V / Phase-H decompositions
    const int  vcol  = tid % IWW;
    const int  vrg   = tid / IWW;
    const int  hrow  = tid & 31;
    const int  hcg   = tid >> 5;

    float lsum = 0.f;

    for (int work = blockIdx.x; work < NWORK; work += GRID) {
        const int tile = work & (NTILE - 1);
        const int ic   = work >> 5;
        const int ty = tile >> 2, tx = tile & 3;
        const int h0 = ty * TH, w0 = tx * TW;
        const int n  = ic / CHN;

        const float* xp = pred   + ic * NPIX;
        const float* yp = target + ic * NPIX;
        const unsigned char* wb = g_wbonus + n * NPIX;

        __syncthreads();   // prev iteration fully done with SMEM

        // ---- Phase 1: halo load + L1/weighted-L1 fold ----
        if (cok) {
            const int  gw   = w0 - 5 + c1;
            const bool gwok = (gw >= 0) && (gw < WW);
            #pragma unroll
            for (int it = 0; it < 11; it++) {
                int r = r1 + 4 * it;
                if (r1 < 2 || it < 10) {            // r < IHH
                    int gh = h0 - 5 + r;
                    bool ok = gwok && (gh >= 0) && (gh < HH);
                    int  off = gh * WW + gw;
                    float xv = 0.f, yv = 0.f;
                    if (ok) { xv = xp[off]; yv = yp[off]; }
                    sXY[r * XP2 + c1] = make_float2(xv, yv);
                    if (cint && r >= 5 && r < IHH - 5) {
                        float ad    = fabsf(xv - yv);
                        float bonus = (float)wb[off];
                        lsum += (15.f + 5.f * bonus) * ad;   // 10*ad + 5*(1+b)*ad
                    }
                }
            }
        }
        __syncthreads();

        // ---- Phase V: vertical conv, packed pairs, 8-row blocking ----
        if (tid < IWW * 4) {
            u64 aMU[8], aSQ[8];
            #pragma unroll
            for (int o = 0; o < 8; o++) { aMU[o] = 0ull; aSQ[o] = 0ull; }
            #pragma unroll
            for (int k = 0; k < 18; k++) {
                float2 p  = sXY[(vrg * 8 + k) * XP2 + vcol];
                u64 mu2 = pack2(p.x, p.y);
                u64 sq2 = pack2(fmaf(p.x, p.x, p.y * p.y), p.x * p.y);
                #pragma unroll
                for (int o = 0; o < 8; o++) {
                    int t = k - o;
                    if (t >= 0 && t < 11) {
                        u64 gg = G2[(t <= 5) ? t : 10 - t];
                        aMU[o] = ffma2(gg, mu2, aMU[o]);
                        aSQ[o] = ffma2(gg, sq2, aSQ[o]);
                    }
                }
            }
            #pragma unroll
            for (int o = 0; o < 8; o++) {
                ulonglong2 v; v.x = aMU[o]; v.y = aSQ[o];
                Vb[(vrg * 8 + o) * VP4 + vcol] = v;         // STS.128
            }
        }
        __syncthreads();

        // ---- Phase H: horizontal conv (LDS.128), packed pairs + dssim ----
        if (tid < 256) {
            const ulonglong2* vrow = Vb + hrow * VP4 + hcg * 8;
            u64 aMU[8], aSQ[8];
            #pragma unroll
            for (int o = 0; o < 8; o++) { aMU[o] = 0ull; aSQ[o] = 0ull; }
            #pragma unroll
            for (int k = 0; k < 18; k++) {
                ulonglong2 v = vrow[k];
                #pragma unroll
                for (int o = 0; o < 8; o++) {
                    int t = k - o;
                    if (t >= 0 && t < 11) {
                        u64 gg = G2[(t <= 5) ? t : 10 - t];
                        aMU[o] = ffma2(gg, v.x, aMU[o]);
                        aSQ[o] = ffma2(gg, v.y, aSQ[o]);
                    }
                }
            }
            const float C1 = 0.01f * 0.01f;
            const float C2 = 0.03f * 0.03f;
            #pragma unroll
            for (int o = 0; o < 8; o++) {
                float mux, muy, ss, xy;
                unpack2(aMU[o], mux, muy);
                unpack2(aSQ[o], ss, xy);
                float sxy  = xy - mux * muy;
                float ssum = ss - mux * mux - muy * muy;    // sigma_x + sigma_y
                float num = (2.f * mux * muy + C1) * (2.f * sxy + C2);
                float den = (mux * mux + muy * muy + C1) * (ssum + C2);
                float ssim = num / (den + 1e-8f);
                lsum += 10.f * 0.5f * (1.f - ssim);
            }
        }
    }

    // ---- Final reduce (once per block) ----
    #pragma unroll
    for (int s = 16; s > 0; s >>= 1)
        lsum += __shfl_xor_sync(0xFFFFFFFFu, lsum, s);
    if ((tid & 31) == 0) red[tid >> 5] = lsum;
    __syncthreads();
    if (tid == 0) {
        float t = 0.f;
        #pragma unroll
        for (int i = 0; i < NTHR / 32; i++) t += red[i];
        atomicAdd(&g_acc, (double)t);
        __threadfence();
        unsigned int old = atomicAdd(&g_count, 1u);
        if (old == GRID - 1) {
            double v = atomicAdd(&g_acc, 0.0);   // coherent read of final sum
            out[0] = (float)(v * (1.0 / (double)(NB * CHN * NPIX)));
            g_count = 0;                          // reset for next graph replay
        }
    }
}

extern "C" void kernel_launch(void* const* d_in, const int* in_sizes, int n_in,
                              void* d_out, int out_size) {
    (void)in_sizes; (void)n_in; (void)out_size;
    const float* pred   = (const float*)d_in[0];
    const float* target = (const float*)d_in[1];
    const float* lmk    = (const float*)d_in[2];
    float* out = (float*)d_out;

    cudaFuncSetAttribute(main_kernel, cudaFuncAttributeMaxDynamicSharedMemorySize,
                         SM_BYTES);

    wmap_kernel<<<dim3(HH / 8, NB), WW>>>(lmk);
    main_kernel<<<GRID, NTHR, SM_BYTES>>>(pred, target, out);
}

// round 10
// speedup vs baseline: 1.0266x; 1.0266x over previous
#include <cuda_runtime.h>

#define NB   48
#define CHN  3
#define HH   256
#define WW   256
#define NIC  (NB*CHN)
#define NPIX (HH*WW)

#define TH   32
#define TW   64
#define PW   80              // plane stride (floats); rows 16B-aligned
#define PLANE (42*PW)        // one x or y halo plane (42 rows)
#define VP4  75              // Vb float4 stride: 12r mod 32 distinct -> conflict-free
#define NTHR 320
#define NTILE 32
#define NWORK (NTILE * NIC)  // 4608 tiles
#define GRID  296            // 2 blocks/SM * 148 SMs, persistent

// floats: 4 planes (x0,y0,x1,y1) + Vb; then wbuf (2*512 u32) + red
#define SM_BYTES ((4*PLANE + 4*TH*VP4)*4 + 2*2048 + 64)

__device__ double g_acc;
__device__ unsigned int g_count = 0;
__device__ unsigned char g_wbonus[NB * NPIX];   // 3*m0 + 3*m1 + 2*m2 in [0,8]

// Normalized 1D Gaussian, k=11, sigma=1.5
__device__ constexpr float G[11] = {
    0.00102838f, 0.00759876f, 0.03600078f, 0.10936071f, 0.21300554f,
    0.26601172f,
    0.21300554f, 0.10936071f, 0.03600078f, 0.00759876f, 0.00102838f
};

__device__ __forceinline__ unsigned smem_addr(const void* p) {
    unsigned r;
    asm("{ .reg .u64 t; cvta.to.shared.u64 t, %1; cvt.u32.u64 %0, t; }"
        : "=r"(r) : "l"(p));
    return r;
}
__device__ __forceinline__ void cp_async16(unsigned dst, const void* src, unsigned sz) {
    asm volatile("cp.async.cg.shared.global [%0], [%1], 16, %2;"
                 :: "r"(dst), "l"(src), "r"(sz) : "memory");
}
__device__ __forceinline__ void cp_commit() {
    asm volatile("cp.async.commit_group;" ::: "memory");
}
__device__ __forceinline__ void cp_wait0() {
    asm volatile("cp.async.wait_group 0;" ::: "memory");
}

// 8 rows per block; crossing-threshold compaction (unchanged from R8).
__global__ void __launch_bounds__(WW) wmap_kernel(const float* __restrict__ lmk) {
    const int rbase = blockIdx.x * 8;
    const int n     = blockIdx.y;
    const int tid   = threadIdx.x;

    __shared__ float ethr[8][24];
    __shared__ int   eflg[8][24];
    __shared__ float clist[8][3][12];
    __shared__ int   ccnt[8][3];
    __shared__ float bxmin[3], bxmax[3], fymn[3], fymx[3];
    __shared__ int   pval[3];

    if (rbase == 0 && n == 0 && tid == 255) g_acc = 0.0;  // zero per replay

    const float* L = lmk + n * 136;

    if (tid < 192) {
        int rr = tid / 24, e = tid % 24;
        float Y = (float)(rbase + rr);
        int p    = (e < 6) ? 0 : ((e < 12) ? 1 : 2);
        int base = (p == 0) ? 36 : ((p == 1) ? 42 : 48);
        int cnt  = (p == 2) ? 12 : 6;
        int i    = e - ((p == 0) ? 0 : ((p == 1) ? 6 : 12));
        int j    = (i + 1 == cnt) ? 0 : i + 1;
        float x1 = L[2*(base+i)], y1 = L[2*(base+i)+1];
        float x2 = L[2*(base+j)], y2 = L[2*(base+j)+1];
        eflg[rr][e] = ((y1 > Y) != (y2 > Y)) ? 1 : 0;
        ethr[rr][e] = (x2 - x1) * (Y - y1) / (y2 - y1 + 1e-6f) + x1;
    } else if (tid < 195) {
        int p    = tid - 192;
        int base = (p == 0) ? 36 : ((p == 1) ? 42 : 48);
        int cnt  = (p == 2) ? 12 : 6;
        float mnx = 1e30f, mxx = -1e30f, mny = 1e30f, mxy = -1e30f;
        for (int i = 0; i < cnt; i++) {
            float x = L[2*(base+i)], y = L[2*(base+i)+1];
            mnx = fminf(mnx, x); mxx = fmaxf(mxx, x);
            mny = fminf(mny, y); mxy = fmaxf(mxy, y);
        }
        float fxmin = floorf(mnx), fxmax = floorf(mxx);
        fymn[p] = floorf(mny);  fymx[p] = floorf(mxy);
        pval[p] = ((fxmin >= 0.f) && (fymn[p] >= 0.f) &&
                   (fxmax < (float)WW) && (fymx[p] < (float)HH)) ? 1 : 0;
        bxmin[p] = fxmin; bxmax[p] = fxmax;
    }
    __syncthreads();

    if (tid < 24) {
        int rr = tid / 3, p = tid % 3;
        float Y = (float)(rbase + rr);
        int s  = (p == 0) ? 0 : ((p == 1) ? 6 : 12);
        int cn = (p == 2) ? 12 : 6;
        int c = 0;
        if (pval[p] && (Y >= fymn[p]) && (Y < fymx[p])) {
            for (int i = 0; i < cn; i++)
                if (eflg[rr][s + i]) clist[rr][p][c++] = ethr[rr][s + i];
        }
        ccnt[rr][p] = c;
    }
    __syncthreads();

    unsigned char* dst = g_wbonus + n * NPIX + rbase * WW;
    float X = (float)tid;
    #pragma unroll
    for (int r = 0; r < 8; r++) {
        int c0 = ccnt[r][0], c1 = ccnt[r][1], c2 = ccnt[r][2];
        int bonus = 0;
        if ((c0 | c1 | c2) != 0) {
            int cnt = 0;
            for (int i = 0; i < c0; i++) cnt += (X < clist[r][0][i]) ? 1 : 0;
            if ((cnt & 1) && (X >= bxmin[0]) && (X < bxmax[0])) bonus += 3;
            cnt = 0;
            for (int i = 0; i < c1; i++) cnt += (X < clist[r][1][i]) ? 1 : 0;
            if ((cnt & 1) && (X >= bxmin[1]) && (X < bxmax[1])) bonus += 3;
            cnt = 0;
            for (int i = 0; i < c2; i++) cnt += (X < clist[r][2][i]) ? 1 : 0;
            if ((cnt & 1) && (X >= bxmin[2]) && (X < bxmax[2])) bonus += 2;
        }
        dst[r * WW + tid] = (unsigned char)bonus;
    }
}

// ---------------------------------------------------------------------------
// Persistent fused main with cp.async double-buffered halo pipeline.
// Local plane layout: local col 3+c <-> global col w0-5+c (c in 0..73);
// interior local cols 8..71 (16B aligned for cp.async), side halos 3..7 / 72..76.
// ---------------------------------------------------------------------------
__global__ void __launch_bounds__(NTHR, 2) main_kernel(const float* __restrict__ pred,
                                                       const float* __restrict__ target,
                                                       float* __restrict__ out) {
    extern __shared__ float sm[];
    // planes: buffer b -> X at sm + (2b)*PLANE, Y at sm + (2b+1)*PLANE
    float*    VbF  = sm + 4*PLANE;
    float4*   Vb   = (float4*)VbF;                       // [TH][VP4]
    unsigned* wbuf = (unsigned*)(VbF + 4*TH*VP4);        // [2][512] words
    float*    red  = (float*)(wbuf + 1024);              // [10]

    const int tid = threadIdx.x;
    const unsigned smbase = smem_addr(sm);

    // fixed phase decompositions
    const int vrg  = tid / 74;                 // V: 0..3 valid (tid<296)
    const int vcol = tid - 74 * vrg;
    const int hrow = tid & 31;                 // H
    const int hcg  = tid >> 5;

    float lsum = 0.f;

    // ---- prefetch issue helpers (as code blocks via macros) ----
    // interior cp.async for tile 'wn' into buffer b
    #define ISSUE_INTERIOR(wn, b)                                              \
    {                                                                          \
        int tile_ = (wn) & (NTILE - 1);                                        \
        int ic_   = (wn) >> 5;                                                 \
        int h0_ = (tile_ >> 2) * TH, w0_ = (tile_ & 3) * TW;                   \
        int n_  = ic_ / CHN;                                                   \
        const float* xb_ = pred   + ic_ * NPIX;                                \
        const float* yb_ = target + ic_ * NPIX;                                \
        for (int i = tid; i < 1344; i += NTHR) {                               \
            int a_   = i / 672;                                                \
            int rem_ = i - a_ * 672;                                           \
            int r_ = rem_ >> 4, k_ = rem_ & 15;                                \
            int gh_ = h0_ - 5 + r_;                                            \
            unsigned sz_ = (gh_ >= 0 && gh_ < HH) ? 16u : 0u;                  \
            int ghc_ = gh_ < 0 ? 0 : (gh_ > 255 ? 255 : gh_);                  \
            const float* src_ = (a_ ? yb_ : xb_) + ghc_ * WW + w0_ + k_ * 4;   \
            unsigned dst_ = smbase +                                           \
                (unsigned)(((2*(b) + a_) * PLANE + r_ * PW + 8 + 4*k_) * 4);   \
            cp_async16(dst_, src_, sz_);                                       \
        }                                                                      \
        if (tid < 128) {                                                       \
            int r_ = tid >> 2, k_ = tid & 3;                                   \
            const unsigned char* src_ =                                        \
                g_wbonus + n_ * NPIX + (h0_ + r_) * WW + w0_ + k_ * 16;        \
            unsigned dst_ = smbase + (unsigned)((4*PLANE + 4*TH*VP4) * 4       \
                            + (b) * 2048 + r_ * 64 + k_ * 16);                 \
            cp_async16(dst_, src_, 16u);                                       \
        }                                                                      \
    }

    // ---- prologue: fill buffer 0 for first tile ----
    int p = 0;
    {
        int work0 = blockIdx.x;                 // < GRID <= NWORK
        ISSUE_INTERIOR(work0, 0);
        cp_commit();
        // side halos synchronously
        int tile_ = work0 & (NTILE - 1), ic_ = work0 >> 5;
        int h0_ = (tile_ >> 2) * TH, w0_ = (tile_ & 3) * TW;
        const float* xb_ = pred + ic_ * NPIX;
        const float* yb_ = target + ic_ * NPIX;
        #pragma unroll
        for (int q = 0; q < 3; q++) {
            int i = tid + NTHR * q;
            if (i < 840) {
                int a_ = i / 420, rem_ = i - a_ * 420;
                int r_ = rem_ / 10, cc_ = rem_ - r_ * 10;
                int gcol = (cc_ < 5) ? (w0_ - 5 + cc_) : (w0_ + 59 + cc_);
                int gh_  = h0_ - 5 + r_;
                bool ok  = (gh_ >= 0 && gh_ < HH && gcol >= 0 && gcol < WW);
                float v = ok ? ((a_ ? yb_ : xb_)[gh_ * WW + gcol]) : 0.f;
                int lc = (cc_ < 5) ? (3 + cc_) : (67 + cc_);
                sm[a_ * PLANE + r_ * PW + lc] = v;
            }
        }
        cp_wait0();
        __syncthreads();
    }

    // ---- persistent tile loop ----
    for (int work = blockIdx.x; work < NWORK; work += GRID) {
        const int wn = work + GRID;              // next tile for this block
        const bool havenext = (wn < NWORK);

        // A: issue async prefetch of next tile into buffer p^1
        if (havenext) {
            ISSUE_INTERIOR(wn, p ^ 1);
            cp_commit();
        }

        // side-halo register prefetch for next tile
        float ph0 = 0.f, ph1 = 0.f, ph2 = 0.f;
        if (havenext) {
            int tile_ = wn & (NTILE - 1), ic_ = wn >> 5;
            int h0_ = (tile_ >> 2) * TH, w0_ = (tile_ & 3) * TW;
            const float* xb_ = pred + ic_ * NPIX;
            const float* yb_ = target + ic_ * NPIX;
            #pragma unroll
            for (int q = 0; q < 3; q++) {
                int i = tid + NTHR * q;
                if (i < 840) {
                    int a_ = i / 420, rem_ = i - a_ * 420;
                    int r_ = rem_ / 10, cc_ = rem_ - r_ * 10;
                    int gcol = (cc_ < 5) ? (w0_ - 5 + cc_) : (w0_ + 59 + cc_);
                    int gh_  = h0_ - 5 + r_;
                    bool ok  = (gh_ >= 0 && gh_ < HH && gcol >= 0 && gcol < WW);
                    float v = ok ? ((a_ ? yb_ : xb_)[gh_ * WW + gcol]) : 0.f;
                    if (q == 0) ph0 = v; else if (q == 1) ph1 = v; else ph2 = v;
                }
            }
        }

        const float* Xc = sm + (2 * p) * PLANE;
        const float* Yc = sm + (2 * p + 1) * PLANE;

        // D: L1 + weighted-L1 fold from staged interior + wbonus
        {
            const unsigned* wcur = wbuf + (p ? 512 : 0);
            for (int w = tid; w < 512; w += NTHR) {
                unsigned b4 = wcur[w];
                int r = w >> 4, k = w & 15;
                int base = (r + 5) * PW + 8 + 4 * k;
                #pragma unroll
                for (int j = 0; j < 4; j++) {
                    float xv = Xc[base + j], yv = Yc[base + j];
                    float ad = fabsf(xv - yv);
                    float bb = (float)((b4 >> (8 * j)) & 255u);
                    lsum += (15.f + 5.f * bb) * ad;   // 10*ad + 5*(1+b)*ad
                }
            }
        }

        // E: vertical conv of 4 fields, 8-row blocking (296 threads)
        if (tid < 296) {
            float amx[8], amy[8], ass[8], axy[8];
            #pragma unroll
            for (int o = 0; o < 8; o++) { amx[o]=0.f; amy[o]=0.f; ass[o]=0.f; axy[o]=0.f; }
            #pragma unroll
            for (int k = 0; k < 18; k++) {
                int idx = (8 * vrg + k) * PW + 3 + vcol;
                float xv = Xc[idx], yv = Yc[idx];
                float ss = fmaf(xv, xv, yv * yv);
                float xy = xv * yv;
                #pragma unroll
                for (int o = 0; o < 8; o++) {
                    int t = k - o;
                    if (t >= 0 && t < 11) {
                        float gg = G[t];
                        amx[o] = fmaf(gg, xv, amx[o]);
                        amy[o] = fmaf(gg, yv, amy[o]);
                        ass[o] = fmaf(gg, ss, ass[o]);
                        axy[o] = fmaf(gg, xy, axy[o]);
                    }
                }
            }
            #pragma unroll
            for (int o = 0; o < 8; o++)
                Vb[(8 * vrg + o) * VP4 + vcol] =
                    make_float4(amx[o], amy[o], ass[o], axy[o]);   // STS.128
        }
        __syncthreads();

        // F: horizontal conv (LDS.128) + dssim (256 threads)
        if (tid < 256) {
            const float4* vrow = Vb + hrow * VP4 + hcg * 8;
            float4 a[8];
            #pragma unroll
            for (int o = 0; o < 8; o++) a[o] = make_float4(0.f, 0.f, 0.f, 0.f);
            #pragma unroll
            for (int k = 0; k < 18; k++) {
                float4 v = vrow[k];
                #pragma unroll
                for (int o = 0; o < 8; o++) {
                    int t = k - o;
                    if (t >= 0 && t < 11) {
                        float gg = G[t];
                        a[o].x = fmaf(gg, v.x, a[o].x);
                        a[o].y = fmaf(gg, v.y, a[o].y);
                        a[o].z = fmaf(gg, v.z, a[o].z);
                        a[o].w = fmaf(gg, v.w, a[o].w);
                    }
                }
            }
            const float C1 = 0.01f * 0.01f;
            const float C2 = 0.03f * 0.03f;
            #pragma unroll
            for (int o = 0; o < 8; o++) {
                float mux = a[o].x, muy = a[o].y;
                float sxy  = a[o].w - mux * muy;
                float ssum = a[o].z - mux * mux - muy * muy;   // sigma_x+sigma_y
                float num = (2.f * mux * muy + C1) * (2.f * sxy + C2);
                float den = (mux * mux + muy * muy + C1) * (ssum + C2);
                float ssim = num / (den + 1e-8f);
                lsum += 10.f * 0.5f * (1.f - ssim);
            }
        }

        // B: store side-halo prefetch registers into buffer p^1
        if (havenext) {
            int tile_ = wn & (NTILE - 1);
            int w0_ = (tile_ & 3) * TW; (void)w0_;
            #pragma unroll
            for (int q = 0; q < 3; q++) {
                int i = tid + NTHR * q;
                if (i < 840) {
                    int a_ = i / 420, rem_ = i - a_ * 420;
                    int r_ = rem_ / 10, cc_ = rem_ - r_ * 10;
                    int lc = (cc_ < 5) ? (3 + cc_) : (67 + cc_);
                    float v = (q == 0) ? ph0 : ((q == 1) ? ph1 : ph2);
                    sm[(2 * (p ^ 1) + a_) * PLANE + r_ * PW + lc] = v;
                }
            }
        }

        cp_wait0();
        __syncthreads();
        p ^= 1;
    }

    // ---- final reduce: shuffles -> partials -> one double atomic ----
    #pragma unroll
    for (int s = 16; s > 0; s >>= 1)
        lsum += __shfl_xor_sync(0xFFFFFFFFu, lsum, s);
    if ((tid & 31) == 0) red[tid >> 5] = lsum;
    __syncthreads();
    if (tid == 0) {
        float t = 0.f;
        #pragma unroll
        for (int i = 0; i < NTHR / 32; i++) t += red[i];
        atomicAdd(&g_acc, (double)t);
        __threadfence();
        unsigned int old = atomicAdd(&g_count, 1u);
        if (old == GRID - 1) {
            double v = atomicAdd(&g_acc, 0.0);   // coherent read of final sum
            out[0] = (float)(v * (1.0 / (double)(NB * CHN * NPIX)));
            g_count = 0;                          // reset for next graph replay
        }
    }
    #undef ISSUE_INTERIOR
}

extern "C" void kernel_launch(void* const* d_in, const int* in_sizes, int n_in,
                              void* d_out, int out_size) {
    (void)in_sizes; (void)n_in; (void)out_size;
    const float* pred   = (const float*)d_in[0];
    const float* target = (const float*)d_in[1];
    const float* lmk    = (const float*)d_in[2];
    float* out = (float*)d_out;

    cudaFuncSetAttribute(main_kernel, cudaFuncAttributeMaxDynamicSharedMemorySize,
                         SM_BYTES);

    wmap_kernel<<<dim3(HH / 8, NB), WW>>>(lmk);
    main_kernel<<<GRID, NTHR, SM_BYTES>>>(pred, target, out);
}